// round 2
// baseline (speedup 1.0000x reference)
#include <cuda_runtime.h>

static constexpr int   D      = 2048;
static constexpr int   BMAX   = 8192;
static constexpr float EPS_F  = 1e-8f;
static constexpr float MARGIN = 0.2f;

// Scratch (no device allocation allowed in kernel_launch)
__device__ float g_norm_img[BMAX];
__device__ float g_norm_text[BMAX];
__device__ float g_posdist[BMAX];
__device__ float g_loss[BMAX];

__device__ __forceinline__ float dot4(float4 a, float4 b) {
    return a.x * b.x + a.y * b.y + a.z * b.z + a.w * b.w;
}

// ---------------------------------------------------------------------------
// Kernel A: per-row ||img||, ||text||, img·text -> cosine outputs + scratch.
// One block per row, 256 threads, float4 loads.
// ---------------------------------------------------------------------------
__global__ void __launch_bounds__(256) norms_kernel(
    const float* __restrict__ img, const float* __restrict__ txt,
    float* __restrict__ out, int B, int write_cos)
{
    const int i = blockIdx.x;
    const float4* ip = reinterpret_cast<const float4*>(img + (size_t)i * D);
    const float4* tp = reinterpret_cast<const float4*>(txt + (size_t)i * D);

    float sii = 0.f, stt = 0.f, sit = 0.f;
    #pragma unroll
    for (int j = threadIdx.x; j < D / 4; j += 256) {
        float4 a = ip[j];
        float4 b = tp[j];
        sii += dot4(a, a);
        stt += dot4(b, b);
        sit += dot4(a, b);
    }

    __shared__ float sh[3][8];
    const int lane = threadIdx.x & 31;
    const int w    = threadIdx.x >> 5;
    #pragma unroll
    for (int o = 16; o; o >>= 1) {
        sii += __shfl_down_sync(0xffffffffu, sii, o);
        stt += __shfl_down_sync(0xffffffffu, stt, o);
        sit += __shfl_down_sync(0xffffffffu, sit, o);
    }
    if (lane == 0) { sh[0][w] = sii; sh[1][w] = stt; sh[2][w] = sit; }
    __syncthreads();

    if (threadIdx.x == 0) {
        sii = 0.f; stt = 0.f; sit = 0.f;
        #pragma unroll
        for (int k = 0; k < 8; k++) {
            sii += sh[0][k]; stt += sh[1][k]; sit += sh[2][k];
        }
        float ni = sqrtf(sii);
        float nt = sqrtf(stt);
        float n  = ni * nt;
        float cosv = sit / n;                 // unclamped (cosine outputs)
        g_norm_img[i]  = ni;
        g_norm_text[i] = nt;
        g_posdist[i]   = 1.f - sit / fmaxf(n, EPS_F);  // clamped (loss path)
        if (write_cos) {
            out[1 + i]     = cosv;            // i2t_cosine
            out[1 + B + i] = cosv;            // t2i_cosine (identical by symmetry)
        }
    }
}

// ---------------------------------------------------------------------------
// Kernel B: per-row 4 gathered cross-dots; fused mining (min distance,
// tie -> candidate 1, matching `d1 <= d0`) + both hinge losses.
// Candidate indices are int32 (JAX downcasts int64 without x64 mode).
// ---------------------------------------------------------------------------
__global__ void __launch_bounds__(256) loss_kernel(
    const float* __restrict__ img, const float* __restrict__ txt,
    const int* __restrict__ cand_img,
    const int* __restrict__ cand_text, int B)
{
    const int i = blockIdx.x;
    const int a0 = cand_img[2 * i];      // img candidates (anchor = text_i)
    const int a1 = cand_img[2 * i + 1];
    const int b0 = cand_text[2 * i];     // text candidates (anchor = img_i)
    const int b1 = cand_text[2 * i + 1];

    const float4* T  = reinterpret_cast<const float4*>(txt + (size_t)i  * D);
    const float4* I  = reinterpret_cast<const float4*>(img + (size_t)i  * D);
    const float4* A0 = reinterpret_cast<const float4*>(img + (size_t)a0 * D);
    const float4* A1 = reinterpret_cast<const float4*>(img + (size_t)a1 * D);
    const float4* B0 = reinterpret_cast<const float4*>(txt + (size_t)b0 * D);
    const float4* B1 = reinterpret_cast<const float4*>(txt + (size_t)b1 * D);

    float s0 = 0.f, s1 = 0.f, s2 = 0.f, s3 = 0.f;
    #pragma unroll
    for (int j = threadIdx.x; j < D / 4; j += 256) {
        float4 t  = T[j];
        float4 im = I[j];
        s0 += dot4(t,  A0[j]);
        s1 += dot4(t,  A1[j]);
        s2 += dot4(im, B0[j]);
        s3 += dot4(im, B1[j]);
    }

    __shared__ float sh[4][8];
    const int lane = threadIdx.x & 31;
    const int w    = threadIdx.x >> 5;
    #pragma unroll
    for (int o = 16; o; o >>= 1) {
        s0 += __shfl_down_sync(0xffffffffu, s0, o);
        s1 += __shfl_down_sync(0xffffffffu, s1, o);
        s2 += __shfl_down_sync(0xffffffffu, s2, o);
        s3 += __shfl_down_sync(0xffffffffu, s3, o);
    }
    if (lane == 0) { sh[0][w] = s0; sh[1][w] = s1; sh[2][w] = s2; sh[3][w] = s3; }
    __syncthreads();

    if (threadIdx.x == 0) {
        s0 = 0.f; s1 = 0.f; s2 = 0.f; s3 = 0.f;
        #pragma unroll
        for (int k = 0; k < 8; k++) {
            s0 += sh[0][k]; s1 += sh[1][k]; s2 += sh[2][k]; s3 += sh[3][k];
        }
        const float nt = g_norm_text[i];
        const float ni = g_norm_img[i];

        // t2i negatives: dist(text_i, img_{a*})
        float dA0 = 1.f - s0 / fmaxf(nt * g_norm_img[a0], EPS_F);
        float dA1 = 1.f - s1 / fmaxf(nt * g_norm_img[a1], EPS_F);
        float t2i_neg = (dA1 <= dA0) ? dA1 : dA0;

        // i2t negatives: dist(img_i, text_{b*})
        float dB0 = 1.f - s2 / fmaxf(ni * g_norm_text[b0], EPS_F);
        float dB1 = 1.f - s3 / fmaxf(ni * g_norm_text[b1], EPS_F);
        float i2t_neg = (dB1 <= dB0) ? dB1 : dB0;

        const float pd = g_posdist[i];
        g_loss[i] = fmaxf(pd - i2t_neg + MARGIN, 0.f)
                  + fmaxf(pd - t2i_neg + MARGIN, 0.f);
    }
}

// ---------------------------------------------------------------------------
// Kernel C: deterministic reduction of per-row losses -> out[0]
// ---------------------------------------------------------------------------
__global__ void __launch_bounds__(256) finalize_kernel(float* __restrict__ out, int B)
{
    float s = 0.f;
    for (int j = threadIdx.x; j < B; j += 256) s += g_loss[j];

    __shared__ float sh[8];
    const int lane = threadIdx.x & 31;
    const int w    = threadIdx.x >> 5;
    #pragma unroll
    for (int o = 16; o; o >>= 1) s += __shfl_down_sync(0xffffffffu, s, o);
    if (lane == 0) sh[w] = s;
    __syncthreads();
    if (threadIdx.x == 0) {
        s = 0.f;
        #pragma unroll
        for (int k = 0; k < 8; k++) s += sh[k];
        out[0] = s / (float)B;   // mean(i2t) + mean(t2i) == sum(per-row)/B
    }
}

extern "C" void kernel_launch(void* const* d_in, const int* in_sizes, int n_in,
                              void* d_out, int out_size)
{
    (void)n_in;
    const float* img  = (const float*)d_in[0];   // img_embedding [B, D] fp32
    const float* txt  = (const float*)d_in[1];   // text_embedding [B, D] fp32
    // d_in[2] = labels (unused), d_in[3] = locations (unused)
    const int*   cimg = (const int*)d_in[4];     // cand_img [B, 2] int32
    const int*   ctxt = (const int*)d_in[5];     // cand_text [B, 2] int32
    float* out = (float*)d_out;

    const int B = in_sizes[2];                   // labels element count == batch
    const int write_cos = (out_size >= 1 + 2 * B) ? 1 : 0;

    norms_kernel<<<B, 256>>>(img, txt, out, B, write_cos);
    loss_kernel<<<B, 256>>>(img, txt, cimg, ctxt, B);
    finalize_kernel<<<1, 256>>>(out, B);
}

// round 3
// speedup vs baseline: 1.3756x; 1.3756x over previous
#include <cuda_runtime.h>

static constexpr int   D      = 2048;
static constexpr int   BMAX   = 8192;
static constexpr float EPS_F  = 1e-8f;
static constexpr float MARGIN = 0.2f;

// Scratch (device globals; no allocation allowed)
__device__ float g_norm_img[BMAX];
__device__ float g_norm_text[BMAX];
__device__ float g_posdist[BMAX];
__device__ float g_cos[BMAX];
__device__ float g_s[4][BMAX];     // raw cross-dots: tA0, tA1, iB0, iB1
__device__ float g_partial[64];    // per-block partial loss sums

__device__ __forceinline__ float dot4(float4 a, float4 b) {
    return a.x * b.x + a.y * b.y + a.z * b.z + a.w * b.w;
}

// ---------------------------------------------------------------------------
// Kernel 1 (fused): one block per row. Single pass over 6 rows computes
// ||img_i||, ||text_i||, img_i·text_i, and the 4 candidate cross-dots.
// ---------------------------------------------------------------------------
__global__ void __launch_bounds__(256) fused_main_kernel(
    const float* __restrict__ img, const float* __restrict__ txt,
    const int* __restrict__ cand_img, const int* __restrict__ cand_text)
{
    const int i  = blockIdx.x;
    const int a0 = cand_img[2 * i];      // img candidates (anchor = text_i)
    const int a1 = cand_img[2 * i + 1];
    const int b0 = cand_text[2 * i];     // text candidates (anchor = img_i)
    const int b1 = cand_text[2 * i + 1];

    const float4* I  = reinterpret_cast<const float4*>(img + (size_t)i  * D);
    const float4* T  = reinterpret_cast<const float4*>(txt + (size_t)i  * D);
    const float4* A0 = reinterpret_cast<const float4*>(img + (size_t)a0 * D);
    const float4* A1 = reinterpret_cast<const float4*>(img + (size_t)a1 * D);
    const float4* B0 = reinterpret_cast<const float4*>(txt + (size_t)b0 * D);
    const float4* B1 = reinterpret_cast<const float4*>(txt + (size_t)b1 * D);

    float sii = 0.f, stt = 0.f, sit = 0.f;
    float s0 = 0.f, s1 = 0.f, s2 = 0.f, s3 = 0.f;

    #pragma unroll
    for (int j = threadIdx.x; j < D / 4; j += 256) {
        float4 a  = I[j];
        float4 t  = T[j];
        float4 c0 = A0[j];
        float4 c1 = A1[j];
        float4 c2 = B0[j];
        float4 c3 = B1[j];
        sii += dot4(a, a);
        stt += dot4(t, t);
        sit += dot4(a, t);
        s0  += dot4(t, c0);
        s1  += dot4(t, c1);
        s2  += dot4(a, c2);
        s3  += dot4(a, c3);
    }

    __shared__ float sh[7][8];
    const int lane = threadIdx.x & 31;
    const int w    = threadIdx.x >> 5;
    #pragma unroll
    for (int o = 16; o; o >>= 1) {
        sii += __shfl_down_sync(0xffffffffu, sii, o);
        stt += __shfl_down_sync(0xffffffffu, stt, o);
        sit += __shfl_down_sync(0xffffffffu, sit, o);
        s0  += __shfl_down_sync(0xffffffffu, s0,  o);
        s1  += __shfl_down_sync(0xffffffffu, s1,  o);
        s2  += __shfl_down_sync(0xffffffffu, s2,  o);
        s3  += __shfl_down_sync(0xffffffffu, s3,  o);
    }
    if (lane == 0) {
        sh[0][w] = sii; sh[1][w] = stt; sh[2][w] = sit;
        sh[3][w] = s0;  sh[4][w] = s1;  sh[5][w] = s2;  sh[6][w] = s3;
    }
    __syncthreads();

    if (threadIdx.x < 32) {
        // 7 sums, one per value of (threadIdx.x / 8 pattern): do it serially on t0
        if (threadIdx.x == 0) {
            float v[7];
            #pragma unroll
            for (int q = 0; q < 7; q++) {
                float acc = 0.f;
                #pragma unroll
                for (int k = 0; k < 8; k++) acc += sh[q][k];
                v[q] = acc;
            }
            float ni = sqrtf(v[0]);
            float nt = sqrtf(v[1]);
            float n  = ni * nt;
            g_norm_img[i]  = ni;
            g_norm_text[i] = nt;
            g_cos[i]       = v[2] / n;                       // unclamped
            g_posdist[i]   = 1.f - v[2] / fmaxf(n, EPS_F);   // clamped
            g_s[0][i] = v[3];
            g_s[1][i] = v[4];
            g_s[2][i] = v[5];
            g_s[3][i] = v[6];
        }
    }
}

// ---------------------------------------------------------------------------
// Kernel 2 (epilogue): per-row scalar math. Mining fused as min-distance
// (tie -> candidate 1, matching `d1 <= d0`), hinge losses, cosine outputs,
// deterministic per-block partial sums.
// ---------------------------------------------------------------------------
__global__ void __launch_bounds__(256) epilogue_kernel(
    const int* __restrict__ cand_img, const int* __restrict__ cand_text,
    float* __restrict__ out, int B, int write_cos)
{
    const int i = blockIdx.x * 256 + threadIdx.x;

    float loss = 0.f;
    if (i < B) {
        const int a0 = cand_img[2 * i];
        const int a1 = cand_img[2 * i + 1];
        const int b0 = cand_text[2 * i];
        const int b1 = cand_text[2 * i + 1];

        const float nt = g_norm_text[i];
        const float ni = g_norm_img[i];

        // t2i negatives: dist(text_i, img_{a*})
        float dA0 = 1.f - g_s[0][i] / fmaxf(nt * g_norm_img[a0], EPS_F);
        float dA1 = 1.f - g_s[1][i] / fmaxf(nt * g_norm_img[a1], EPS_F);
        float t2i_neg = (dA1 <= dA0) ? dA1 : dA0;

        // i2t negatives: dist(img_i, text_{b*})
        float dB0 = 1.f - g_s[2][i] / fmaxf(ni * g_norm_text[b0], EPS_F);
        float dB1 = 1.f - g_s[3][i] / fmaxf(ni * g_norm_text[b1], EPS_F);
        float i2t_neg = (dB1 <= dB0) ? dB1 : dB0;

        const float pd = g_posdist[i];
        loss = fmaxf(pd - i2t_neg + MARGIN, 0.f)
             + fmaxf(pd - t2i_neg + MARGIN, 0.f);

        if (write_cos) {
            const float c = g_cos[i];
            out[1 + i]     = c;   // i2t_cosine
            out[1 + B + i] = c;   // t2i_cosine (identical by symmetry)
        }
    }

    // deterministic in-block reduction of loss
    __shared__ float sh[8];
    const int lane = threadIdx.x & 31;
    const int w    = threadIdx.x >> 5;
    #pragma unroll
    for (int o = 16; o; o >>= 1) loss += __shfl_down_sync(0xffffffffu, loss, o);
    if (lane == 0) sh[w] = loss;
    __syncthreads();
    if (threadIdx.x == 0) {
        float s = 0.f;
        #pragma unroll
        for (int k = 0; k < 8; k++) s += sh[k];
        g_partial[blockIdx.x] = s;
    }
}

// ---------------------------------------------------------------------------
// Kernel 3: final deterministic sum of partials -> out[0]
// ---------------------------------------------------------------------------
__global__ void finalize_kernel(float* __restrict__ out, int nblocks, int B)
{
    if (threadIdx.x == 0) {
        float s = 0.f;
        for (int k = 0; k < nblocks; k++) s += g_partial[k];
        out[0] = s / (float)B;   // mean(i2t) + mean(t2i) == sum(per-row)/B
    }
}

extern "C" void kernel_launch(void* const* d_in, const int* in_sizes, int n_in,
                              void* d_out, int out_size)
{
    (void)n_in;
    const float* img  = (const float*)d_in[0];   // img_embedding [B, D] fp32
    const float* txt  = (const float*)d_in[1];   // text_embedding [B, D] fp32
    // d_in[2] = labels (unused), d_in[3] = locations (unused)
    const int*   cimg = (const int*)d_in[4];     // cand_img [B, 2] int32
    const int*   ctxt = (const int*)d_in[5];     // cand_text [B, 2] int32
    float* out = (float*)d_out;

    const int B = in_sizes[2];                   // labels element count == batch
    const int write_cos = (out_size >= 1 + 2 * B) ? 1 : 0;
    const int eblocks = (B + 255) / 256;         // 32 for B=8192 (g_partial has 64)

    fused_main_kernel<<<B, 256>>>(img, txt, cimg, ctxt);
    epilogue_kernel<<<eblocks, 256>>>(cimg, ctxt, out, B, write_cos);
    finalize_kernel<<<1, 32>>>(out, eblocks, B);
}